// round 1
// baseline (speedup 1.0000x reference)
#include <cuda_runtime.h>
#include <math.h>

#define B_   64
#define L_   32
#define D_   1024
#define DFF  2048
#define K_   128
#define N_   256

// ---------------- scratch (no allocations allowed) ----------------
__device__ float g_A[N_ * N_];              // normalized A  [i][j]
__device__ float g_W[N_ * K_ * K_];         // normalized W  [t][i][o]
__device__ float g_xr[B_ * N_ * K_];        // LN'd kronecker input
__device__ float g_xloc[B_ * N_ * K_];      // x_local [b][n][o]
__device__ float g_xln[B_ * K_ * N_];       // transposed+LN [b][k][n]
__device__ float g_xglob[B_ * K_ * N_];     // x_global [b][k][n]
__device__ float g_mixed[B_ * L_ * D_];
__device__ float g_H[B_ * L_ * DFF];        // silu(gate)*up
__device__ float g_ffn[B_ * L_ * D_];

// ---------------- helpers ----------------
__device__ __forceinline__ void blockReduce2_256(float& s1, float& s2) {
    __shared__ float sh1[8], sh2[8];
    int t = threadIdx.x;
    #pragma unroll
    for (int o = 16; o > 0; o >>= 1) {
        s1 += __shfl_xor_sync(0xffffffffu, s1, o);
        s2 += __shfl_xor_sync(0xffffffffu, s2, o);
    }
    if ((t & 31) == 0) { sh1[t >> 5] = s1; sh2[t >> 5] = s2; }
    __syncthreads();
    float a = 0.f, b = 0.f;
    #pragma unroll
    for (int w = 0; w < 8; w++) { a += sh1[w]; b += sh2[w]; }
    s1 = a; s2 = b;
    __syncthreads();   // protect sh reuse by callers looping
}

// ---------------- K0: A = A_logits / max(||col||, eps) ----------------
__global__ void k_prepA(const float* __restrict__ Al) {
    int j = blockIdx.x;          // column
    int i = threadIdx.x;         // row (256)
    float v = Al[i * N_ + j];
    float s1 = v * v, s2 = 0.f;
    blockReduce2_256(s1, s2);
    float inv = 1.f / fmaxf(sqrtf(s1), 1e-12f);
    g_A[i * N_ + j] = v * inv;
}

// ---------------- K1: W[t] = norm_cols( sum_k W1[t,k] * WV[k] ) ----------------
__global__ void k_prepW(const float* __restrict__ W1, const float* __restrict__ WV) {
    int t = blockIdx.x;          // 256
    int o = threadIdx.x;         // 128
    float w1[8];
    #pragma unroll
    for (int k = 0; k < 8; k++) w1[k] = W1[t * 8 + k];
    float ss = 0.f;
    for (int i = 0; i < K_; i++) {
        float wl = 0.f;
        #pragma unroll
        for (int k = 0; k < 8; k++) wl += w1[k] * WV[(k * K_ + i) * K_ + o];
        ss += wl * wl;
    }
    float inv = 1.f / fmaxf(sqrtf(ss), 1e-12f);
    for (int i = 0; i < K_; i++) {
        float wl = 0.f;
        #pragma unroll
        for (int k = 0; k < 8; k++) wl += w1[k] * WV[(k * K_ + i) * K_ + o];
        g_W[(t * K_ + i) * K_ + o] = wl * inv;
    }
}

// ---------------- K2: xr = LN128( x + LN_D(y) ) ----------------
__global__ void k_xr(const float* __restrict__ x, const float* __restrict__ y,
                     const float* __restrict__ nyg, const float* __restrict__ nyb,
                     const float* __restrict__ kn1g, const float* __restrict__ kn1b) {
    int row = blockIdx.x;        // b*L + l
    int t = threadIdx.x;         // 256, 4 elems each
    const float* yr = y + (size_t)row * D_;
    const float* xp = x + (size_t)row * D_;
    float yv[4];
    float s1 = 0.f, s2 = 0.f;
    #pragma unroll
    for (int e = 0; e < 4; e++) {
        float v = yr[t * 4 + e];
        yv[e] = v; s1 += v; s2 += v * v;
    }
    blockReduce2_256(s1, s2);
    float m = s1 * (1.f / D_);
    float var = s2 * (1.f / D_) - m * m;
    float rs = rsqrtf(var + 1e-5f);
    float kin[4];
    float ls1 = 0.f, ls2 = 0.f;
    #pragma unroll
    for (int e = 0; e < 4; e++) {
        int d = t * 4 + e;
        float ny = (yv[e] - m) * rs * nyg[d] + nyb[d];
        float kv = xp[d] + ny;
        kin[e] = kv; ls1 += kv; ls2 += kv * kv;
    }
    // 128-wide sub-LN: each warp owns exactly one 128-block (32 thr * 4 elems)
    #pragma unroll
    for (int o = 16; o > 0; o >>= 1) {
        ls1 += __shfl_xor_sync(0xffffffffu, ls1, o);
        ls2 += __shfl_xor_sync(0xffffffffu, ls2, o);
    }
    float lm = ls1 * (1.f / 128.f);
    float lv = ls2 * (1.f / 128.f) - lm * lm;
    float lrs = rsqrtf(lv + 1e-5f);
    #pragma unroll
    for (int e = 0; e < 4; e++) {
        int d = t * 4 + e;
        int i = d & 127;
        g_xr[(size_t)row * D_ + d] = (kin[e] - lm) * lrs * kn1g[i] + kn1b[i];
    }
}

// ---------------- K3: x_local[b,n,o] = sum_i xr[b,n,i] * W[n,i,o] ----------------
#define BG 16
__global__ void k_xlocal() {
    int n  = blockIdx.x;
    int b0 = blockIdx.y * BG;
    int o  = threadIdx.x;        // 128
    __shared__ float xs[BG][K_];
    #pragma unroll
    for (int bb = 0; bb < BG; bb++)
        xs[bb][o] = g_xr[((size_t)(b0 + bb) * N_ + n) * K_ + o];
    __syncthreads();
    float acc[BG];
    #pragma unroll
    for (int bb = 0; bb < BG; bb++) acc[bb] = 0.f;
    const float* Wn = g_W + (size_t)n * K_ * K_;
    for (int i = 0; i < K_; i++) {
        float w = Wn[i * K_ + o];
        #pragma unroll
        for (int bb = 0; bb < BG; bb++) acc[bb] += xs[bb][i] * w;
    }
    #pragma unroll
    for (int bb = 0; bb < BG; bb++)
        g_xloc[((size_t)(b0 + bb) * N_ + n) * K_ + o] = acc[bb];
}

// ---------------- K4a: transpose + LN over N (kn2) ----------------
__global__ void k_trln(const float* __restrict__ kn2g, const float* __restrict__ kn2b) {
    int k = blockIdx.x;          // 128
    int b = blockIdx.y;          // 64
    int n = threadIdx.x;         // 256
    float v = g_xloc[((size_t)b * N_ + n) * K_ + k];
    float s1 = v, s2 = v * v;
    blockReduce2_256(s1, s2);
    float m = s1 * (1.f / N_);
    float var = s2 * (1.f / N_) - m * m;
    float rs = rsqrtf(var + 1e-5f);
    g_xln[((size_t)b * K_ + k) * N_ + n] = (v - m) * rs * kn2g[n] + kn2b[n];
}

// ---------------- K4b: x_global = x_ln @ A  (16 k-rows per block) ----------------
__global__ void k_xglob() {
    int b  = blockIdx.x;
    int kg = blockIdx.y;         // 8 groups of 16 k
    int m  = threadIdx.x;        // 256
    __shared__ float rows[16][N_];
    #pragma unroll
    for (int kk = 0; kk < 16; kk++)
        rows[kk][m] = g_xln[((size_t)b * K_ + kg * 16 + kk) * N_ + m];
    __syncthreads();
    float acc[16];
    #pragma unroll
    for (int kk = 0; kk < 16; kk++) acc[kk] = 0.f;
    for (int nn = 0; nn < N_; nn++) {
        float a = g_A[nn * N_ + m];
        #pragma unroll
        for (int kk = 0; kk < 16; kk++) acc[kk] += rows[kk][nn] * a;
    }
    #pragma unroll
    for (int kk = 0; kk < 16; kk++)
        g_xglob[((size_t)b * K_ + kg * 16 + kk) * N_ + m] = acc[kk];
}

// ---------------- K5: mixed = LN( x + 0.5*rule + 0.5*kron , n1) ----------------
// rule_h[b,l,d] = x[b, d/32, l*32 + d%32]
// kron_h[b] flattened == x_global[b] flattened (k*256+n == l*1024+d)
__global__ void k_mixed(const float* __restrict__ x,
                        const float* __restrict__ n1g, const float* __restrict__ n1b) {
    int row = blockIdx.x;        // b*L + l
    int b = row >> 5, l = row & 31;
    int t = threadIdx.x;
    float v[4];
    float s1 = 0.f, s2 = 0.f;
    #pragma unroll
    for (int e = 0; e < 4; e++) {
        int d = t * 4 + e;
        float rule = x[((size_t)b * L_ + (d >> 5)) * D_ + l * 32 + (d & 31)];
        float kron = g_xglob[(size_t)row * D_ + d];
        float xv   = x[(size_t)row * D_ + d];
        float val = xv + 0.5f * rule + 0.5f * kron;
        v[e] = val; s1 += val; s2 += val * val;
    }
    blockReduce2_256(s1, s2);
    float m = s1 * (1.f / D_);
    float var = s2 * (1.f / D_) - m * m;
    float rs = rsqrtf(var + 1e-5f);
    #pragma unroll
    for (int e = 0; e < 4; e++) {
        int d = t * 4 + e;
        g_mixed[(size_t)row * D_ + d] = (v[e] - m) * rs * n1g[d] + n1b[d];
    }
}

// ---------------- K6: gate/up GEMMs + SwishGLU ----------------
// per l: [64 x 1024] @ [1024 x 2048], two weights at once. Tile 64x64x32.
#define KT 32
__global__ void k_gateup(const float* __restrict__ Wg, const float* __restrict__ Wu) {
    int l  = blockIdx.x;
    int nt = blockIdx.y;                 // 32 tiles of 64 over DFF
    int t  = threadIdx.x;                // 256
    int tx = t & 15, ty = t >> 4;
    __shared__ float As[KT][68];         // transposed [k][m]
    __shared__ float Bg[KT][64];
    __shared__ float Bu[KT][64];
    float ag[4][4], au[4][4];
    #pragma unroll
    for (int i = 0; i < 4; i++)
        #pragma unroll
        for (int j = 0; j < 4; j++) { ag[i][j] = 0.f; au[i][j] = 0.f; }

    const float* Am  = g_mixed + (size_t)l * D_;            // row b stride L_*D_
    const float* Bgp = Wg + (size_t)l * D_ * DFF + nt * 64; // row k stride DFF
    const float* Bup = Wu + (size_t)l * D_ * DFF + nt * 64;

    for (int k0 = 0; k0 < D_; k0 += KT) {
        #pragma unroll
        for (int q = t; q < 512; q += 256) {
            int rb = q >> 3, c4 = (q & 7) * 4;
            float4 v = *(const float4*)(Am + (size_t)rb * (L_ * D_) + k0 + c4);
            As[c4 + 0][rb] = v.x; As[c4 + 1][rb] = v.y;
            As[c4 + 2][rb] = v.z; As[c4 + 3][rb] = v.w;
        }
        #pragma unroll
        for (int q = t; q < 512; q += 256) {
            int rk = q >> 4, c4 = (q & 15) * 4;
            *(float4*)&Bg[rk][c4] = *(const float4*)(Bgp + (size_t)(k0 + rk) * DFF + c4);
            *(float4*)&Bu[rk][c4] = *(const float4*)(Bup + (size_t)(k0 + rk) * DFF + c4);
        }
        __syncthreads();
        #pragma unroll
        for (int kk = 0; kk < KT; kk++) {
            float4 a  = *(const float4*)&As[kk][ty * 4];
            float4 bg = *(const float4*)&Bg[kk][tx * 4];
            float4 bu = *(const float4*)&Bu[kk][tx * 4];
            float av[4] = {a.x, a.y, a.z, a.w};
            float gv[4] = {bg.x, bg.y, bg.z, bg.w};
            float uv[4] = {bu.x, bu.y, bu.z, bu.w};
            #pragma unroll
            for (int i = 0; i < 4; i++)
                #pragma unroll
                for (int j = 0; j < 4; j++) {
                    ag[i][j] += av[i] * gv[j];
                    au[i][j] += av[i] * uv[j];
                }
        }
        __syncthreads();
    }
    #pragma unroll
    for (int i = 0; i < 4; i++) {
        int b = ty * 4 + i;
        #pragma unroll
        for (int j = 0; j < 4; j++) {
            int f = nt * 64 + tx * 4 + j;
            float g = ag[i][j], u = au[i][j];
            float sil = g / (1.f + expf(-g));
            g_H[((size_t)b * L_ + l) * DFF + f] = sil * u;
        }
    }
}

// ---------------- K7: down GEMM: [64 x 2048] @ [2048 x 1024] per l ----------------
__global__ void k_down(const float* __restrict__ Wd) {
    int l  = blockIdx.x;
    int nt = blockIdx.y;                 // 16 tiles of 64 over D
    int t  = threadIdx.x;
    int tx = t & 15, ty = t >> 4;
    __shared__ float As[KT][68];
    __shared__ float Bs[KT][64];
    float acc[4][4];
    #pragma unroll
    for (int i = 0; i < 4; i++)
        #pragma unroll
        for (int j = 0; j < 4; j++) acc[i][j] = 0.f;

    const float* Am = g_H + (size_t)l * DFF;                // row b stride L_*DFF
    const float* Bp = Wd + (size_t)l * DFF * D_ + nt * 64;  // row f stride D_

    for (int k0 = 0; k0 < DFF; k0 += KT) {
        #pragma unroll
        for (int q = t; q < 512; q += 256) {
            int rb = q >> 3, c4 = (q & 7) * 4;
            float4 v = *(const float4*)(Am + (size_t)rb * (L_ * DFF) + k0 + c4);
            As[c4 + 0][rb] = v.x; As[c4 + 1][rb] = v.y;
            As[c4 + 2][rb] = v.z; As[c4 + 3][rb] = v.w;
        }
        #pragma unroll
        for (int q = t; q < 512; q += 256) {
            int rk = q >> 4, c4 = (q & 15) * 4;
            *(float4*)&Bs[rk][c4] = *(const float4*)(Bp + (size_t)(k0 + rk) * D_ + c4);
        }
        __syncthreads();
        #pragma unroll
        for (int kk = 0; kk < KT; kk++) {
            float4 a = *(const float4*)&As[kk][ty * 4];
            float4 b = *(const float4*)&Bs[kk][tx * 4];
            float av[4] = {a.x, a.y, a.z, a.w};
            float bv[4] = {b.x, b.y, b.z, b.w};
            #pragma unroll
            for (int i = 0; i < 4; i++)
                #pragma unroll
                for (int j = 0; j < 4; j++) acc[i][j] += av[i] * bv[j];
        }
        __syncthreads();
    }
    #pragma unroll
    for (int i = 0; i < 4; i++) {
        int b = ty * 4 + i;
        #pragma unroll
        for (int j = 0; j < 4; j++) {
            int d = nt * 64 + tx * 4 + j;
            g_ffn[((size_t)b * L_ + l) * D_ + d] = acc[i][j];
        }
    }
}

// ---------------- K8: out = LN(mixed+ffn, n2); y_out = y + ffn ----------------
__global__ void k_final(const float* __restrict__ y,
                        const float* __restrict__ n2g, const float* __restrict__ n2b,
                        float* __restrict__ out) {
    int row = blockIdx.x;
    int t = threadIdx.x;
    float v[4], fv[4];
    float s1 = 0.f, s2 = 0.f;
    #pragma unroll
    for (int e = 0; e < 4; e++) {
        int d = t * 4 + e;
        size_t idx = (size_t)row * D_ + d;
        float f = g_ffn[idx];
        float val = g_mixed[idx] + f;
        v[e] = val; fv[e] = f; s1 += val; s2 += val * val;
    }
    blockReduce2_256(s1, s2);
    float m = s1 * (1.f / D_);
    float var = s2 * (1.f / D_) - m * m;
    float rs = rsqrtf(var + 1e-5f);
    #pragma unroll
    for (int e = 0; e < 4; e++) {
        int d = t * 4 + e;
        size_t idx = (size_t)row * D_ + d;
        out[idx] = (v[e] - m) * rs * n2g[d] + n2b[d];
        out[(size_t)B_ * L_ * D_ + idx] = y[idx] + fv[e];
    }
}

// ---------------- launch ----------------
extern "C" void kernel_launch(void* const* d_in, const int* in_sizes, int n_in,
                              void* d_out, int out_size) {
    const float* x       = (const float*)d_in[0];
    const float* y       = (const float*)d_in[1];
    const float* A_log   = (const float*)d_in[2];
    const float* W_1     = (const float*)d_in[3];
    const float* W_V     = (const float*)d_in[4];
    const float* kn1_g   = (const float*)d_in[5];
    const float* kn1_b   = (const float*)d_in[6];
    const float* kn2_g   = (const float*)d_in[7];
    const float* kn2_b   = (const float*)d_in[8];
    const float* W_gate  = (const float*)d_in[9];
    const float* W_up    = (const float*)d_in[10];
    const float* W_down  = (const float*)d_in[11];
    const float* ny_g    = (const float*)d_in[12];
    const float* ny_b    = (const float*)d_in[13];
    const float* n1_g    = (const float*)d_in[14];
    const float* n1_b    = (const float*)d_in[15];
    const float* n2_g    = (const float*)d_in[16];
    const float* n2_b    = (const float*)d_in[17];
    float* out = (float*)d_out;

    k_prepA<<<N_, 256>>>(A_log);
    k_prepW<<<N_, 128>>>(W_1, W_V);
    k_xr<<<B_ * L_, 256>>>(x, y, ny_g, ny_b, kn1_g, kn1_b);
    k_xlocal<<<dim3(N_, B_ / BG), 128>>>();
    k_trln<<<dim3(K_, B_), 256>>>(kn2_g, kn2_b);
    k_xglob<<<dim3(B_, 8), 256>>>();
    k_mixed<<<B_ * L_, 256>>>(x, n1_g, n1_b);
    k_gateup<<<dim3(L_, DFF / 64), 256>>>(W_gate, W_up);
    k_down<<<dim3(L_, D_ / 64), 256>>>(W_down);
    k_final<<<B_ * L_, 256>>>(y, n2_g, n2_b, out);
}